// round 4
// baseline (speedup 1.0000x reference)
#include <cuda_runtime.h>

// Dynamic per-pixel 5x5 conv (KPN) + leaky_relu(0.2), replicate padding.
// x:      (N=4, C=8, H=256, W=256) f32   -> d_in[0]
// kernel: (N=4, C*25=200, H=256, W=256)  -> d_in[1]
// out:    (N=4, C=8, H=256, W=256) f32
//
// Pure HBM-bound problem (~227 MB traffic, ~105 MFLOP). Strategy:
// 4-wide w-vectorization per thread; 25 coalesced float4 kernel-plane loads,
// 40 clamped scalar x loads (x fits in L2, 25x reuse). Branch-free replicate
// padding via min/max clamps.

#define NN   4
#define CC   8
#define HH   256
#define WW   256
#define KK   5
#define PAD  2
#define NEG_SLOPE 0.2f

#define W4   (WW / 4)           // 64
#define HW4  (HH * W4)          // 16384 float4 per plane
#define TOTAL_THREADS (NN * CC * HH * W4)   // 524288

__global__ __launch_bounds__(256) void dynconv_kernel(
    const float* __restrict__ x,
    const float* __restrict__ ker,
    float* __restrict__ out)
{
    int tid = blockIdx.x * blockDim.x + threadIdx.x;
    if (tid >= TOTAL_THREADS) return;

    int w4 = tid & (W4 - 1);
    int h  = (tid >> 6) & (HH - 1);
    int nc = tid >> 14;                 // 0 .. N*C-1 (32)
    int w0 = w4 << 2;

    const float* xbase = x + (size_t)nc * (HH * WW);
    // kernel plane base for (n, c, plane j): planes are contiguous in j for
    // fixed (n,c) since layout is (n, c*25, h, w) with c slowest.
    const float4* kbase = reinterpret_cast<const float4*>(ker)
                        + (size_t)nc * 25 * HW4
                        + (size_t)h * W4 + w4;

    float a0 = 0.f, a1 = 0.f, a2 = 0.f, a3 = 0.f;

    #pragma unroll
    for (int k1 = 0; k1 < KK; k1++) {
        int r = h + k1 - PAD;
        r = max(0, min(HH - 1, r));
        const float* xrow = xbase + r * WW;

        float xv[8];
        #pragma unroll
        for (int i = 0; i < 8; i++) {
            int cidx = w0 + i - PAD;
            cidx = max(0, min(WW - 1, cidx));
            xv[i] = __ldg(xrow + cidx);
        }

        #pragma unroll
        for (int k2 = 0; k2 < KK; k2++) {
            float4 kv = __ldg(kbase + (size_t)(k1 * KK + k2) * HW4);
            a0 = fmaf(xv[k2 + 0], kv.x, a0);
            a1 = fmaf(xv[k2 + 1], kv.y, a1);
            a2 = fmaf(xv[k2 + 2], kv.z, a2);
            a3 = fmaf(xv[k2 + 3], kv.w, a3);
        }
    }

    float4 o;
    o.x = a0 >= 0.f ? a0 : NEG_SLOPE * a0;
    o.y = a1 >= 0.f ? a1 : NEG_SLOPE * a1;
    o.z = a2 >= 0.f ? a2 : NEG_SLOPE * a2;
    o.w = a3 >= 0.f ? a3 : NEG_SLOPE * a3;

    reinterpret_cast<float4*>(out)[tid] = o;
}

extern "C" void kernel_launch(void* const* d_in, const int* in_sizes, int n_in,
                              void* d_out, int out_size)
{
    const float* x   = (const float*)d_in[0];
    const float* ker = (const float*)d_in[1];
    float* out = (float*)d_out;

    dim3 block(256);
    dim3 grid((TOTAL_THREADS + 255) / 256);
    dynconv_kernel<<<grid, block>>>(x, ker, out);
}

// round 6
// speedup vs baseline: 1.0864x; 1.0864x over previous
#include <cuda_runtime.h>

// Dynamic per-pixel 5x5 conv (KPN) + leaky_relu(0.2), replicate padding.
// x:      (N=4, C=8, H=256, W=256) f32   -> d_in[0]
// kernel: (N=4, C*25=200, H=256, W=256)  -> d_in[1]
// out:    (N=4, C=8, H=256, W=256) f32
//
// HBM-bound: traffic already minimal (~227 MB). R5 change: 128-thread CTAs
// with min-blocks 12 -> 48 warps/SM (was 40) to raise outstanding-load count
// and push DRAM% toward ceiling. Row pointers precomputed to shorten the
// address-dependency prefix before the batched loads.

#define NN   4
#define CC   8
#define HH   256
#define WW   256
#define KK   5
#define PAD  2
#define NEG_SLOPE 0.2f

#define W4   (WW / 4)           // 64
#define HW4  (HH * W4)          // 16384 float4 per plane
#define TOTAL_THREADS (NN * CC * HH * W4)   // 524288
#define BLOCK 128

__global__ __launch_bounds__(BLOCK, 12) void dynconv_kernel(
    const float* __restrict__ x,
    const float* __restrict__ ker,
    float* __restrict__ out)
{
    int tid = blockIdx.x * BLOCK + threadIdx.x;

    int w4 = tid & (W4 - 1);
    int h  = (tid >> 6) & (HH - 1);
    int nc = tid >> 14;                 // 0 .. N*C-1 (32)
    int w0 = w4 << 2;

    const float* xbase = x + (size_t)nc * (HH * WW);
    const float4* kbase = reinterpret_cast<const float4*>(ker)
                        + (size_t)nc * 25 * HW4
                        + (size_t)h * W4 + w4;

    // Precompute clamped row pointers (replicate padding in h).
    const float* xrow[KK];
    #pragma unroll
    for (int k1 = 0; k1 < KK; k1++) {
        int r = h + k1 - PAD;
        r = max(0, min(HH - 1, r));
        xrow[k1] = xbase + r * WW;
    }

    float a0 = 0.f, a1 = 0.f, a2 = 0.f, a3 = 0.f;

    #pragma unroll
    for (int k1 = 0; k1 < KK; k1++) {
        const float* row = xrow[k1];

        float xv[8];
        #pragma unroll
        for (int i = 0; i < 8; i++) {
            int cidx = w0 + i - PAD;
            cidx = max(0, min(WW - 1, cidx));
            xv[i] = __ldg(row + cidx);
        }

        #pragma unroll
        for (int k2 = 0; k2 < KK; k2++) {
            float4 kv = __ldg(kbase + (size_t)(k1 * KK + k2) * HW4);
            a0 = fmaf(xv[k2 + 0], kv.x, a0);
            a1 = fmaf(xv[k2 + 1], kv.y, a1);
            a2 = fmaf(xv[k2 + 2], kv.z, a2);
            a3 = fmaf(xv[k2 + 3], kv.w, a3);
        }
    }

    float4 o;
    o.x = a0 >= 0.f ? a0 : NEG_SLOPE * a0;
    o.y = a1 >= 0.f ? a1 : NEG_SLOPE * a1;
    o.z = a2 >= 0.f ? a2 : NEG_SLOPE * a2;
    o.w = a3 >= 0.f ? a3 : NEG_SLOPE * a3;

    reinterpret_cast<float4*>(out)[tid] = o;
}

extern "C" void kernel_launch(void* const* d_in, const int* in_sizes, int n_in,
                              void* d_out, int out_size)
{
    const float* x   = (const float*)d_in[0];
    const float* ker = (const float*)d_in[1];
    float* out = (float*)d_out;

    dynconv_kernel<<<TOTAL_THREADS / BLOCK, BLOCK>>>(x, ker, out);
}

// round 8
// speedup vs baseline: 1.0872x; 1.0008x over previous
#include <cuda_runtime.h>

// Dynamic per-pixel 5x5 conv (KPN) + leaky_relu(0.2), replicate padding.
// x:      (N=4, C=8, H=256, W=256) f32   -> d_in[0]
// kernel: (N=4, C*25=200, H=256, W=256)  -> d_in[1]
// out:    (N=4, C=8, H=256, W=256) f32
//
// R7: 2 output rows per thread (h, h+1). Shared x rows across vertical taps:
// 48 x loads + 50 kernel float4 loads per 8 outputs. ~2x in-flight bytes per
// warp, half the threads. Kernel tensor streamed via __ldcs (zero reuse).

#define NN   4
#define CC   8
#define HH   256
#define WW   256
#define KK   5
#define PAD  2
#define NEG_SLOPE 0.2f

#define W4   (WW / 4)           // 64
#define HW4  (HH * W4)          // 16384 float4 per plane
#define H2   (HH / 2)           // 128 row-pairs
#define TOTAL_THREADS (NN * CC * H2 * W4)   // 262144
#define BLOCK 128

__device__ __forceinline__ float lrelu(float v) {
    return v >= 0.f ? v : NEG_SLOPE * v;
}

__global__ __launch_bounds__(BLOCK, 10) void dynconv_kernel(
    const float* __restrict__ x,
    const float* __restrict__ ker,
    float* __restrict__ out)
{
    int tid = blockIdx.x * BLOCK + threadIdx.x;

    int w4   = tid & (W4 - 1);
    int hblk = (tid >> 6) & (H2 - 1);
    int nc   = tid >> 13;               // 0 .. N*C-1 (32)
    int h0   = hblk << 1;               // even row
    int w0   = w4 << 2;

    const float* xbase = x + (size_t)nc * (HH * WW);
    const float4* kbase0 = reinterpret_cast<const float4*>(ker)
                         + (size_t)nc * 25 * HW4
                         + (size_t)h0 * W4 + w4;
    const float4* kbase1 = kbase0 + W4;   // row h0+1

    // Accumulators: b -> row h0, c -> row h0+1
    float b0 = 0.f, b1 = 0.f, b2 = 0.f, b3 = 0.f;
    float c0 = 0.f, c1 = 0.f, c2 = 0.f, c3 = 0.f;

    // x rows h0-2 .. h0+3 serve taps of both output rows.
    #pragma unroll
    for (int rr = 0; rr < KK + 1; rr++) {
        int r = h0 + rr - PAD;
        r = max(0, min(HH - 1, r));
        const float* row = xbase + r * WW;

        float xv[8];
        #pragma unroll
        for (int i = 0; i < 8; i++) {
            int cidx = w0 + i - PAD;
            cidx = max(0, min(WW - 1, cidx));
            xv[i] = __ldg(row + cidx);
        }

        // tap k1 = rr for output row h0 (valid rr 0..4)
        if (rr < KK) {
            #pragma unroll
            for (int k2 = 0; k2 < KK; k2++) {
                float4 kv = __ldcs(kbase0 + (size_t)(rr * KK + k2) * HW4);
                b0 = fmaf(xv[k2 + 0], kv.x, b0);
                b1 = fmaf(xv[k2 + 1], kv.y, b1);
                b2 = fmaf(xv[k2 + 2], kv.z, b2);
                b3 = fmaf(xv[k2 + 3], kv.w, b3);
            }
        }
        // tap k1 = rr-1 for output row h0+1 (valid rr 1..5)
        if (rr >= 1) {
            #pragma unroll
            for (int k2 = 0; k2 < KK; k2++) {
                float4 kv = __ldcs(kbase1 + (size_t)((rr - 1) * KK + k2) * HW4);
                c0 = fmaf(xv[k2 + 0], kv.x, c0);
                c1 = fmaf(xv[k2 + 1], kv.y, c1);
                c2 = fmaf(xv[k2 + 2], kv.z, c2);
                c3 = fmaf(xv[k2 + 3], kv.w, c3);
            }
        }
    }

    float4 ob, oc;
    ob.x = lrelu(b0); ob.y = lrelu(b1); ob.z = lrelu(b2); ob.w = lrelu(b3);
    oc.x = lrelu(c0); oc.y = lrelu(c1); oc.z = lrelu(c2); oc.w = lrelu(c3);

    float4* out4 = reinterpret_cast<float4*>(out);
    size_t obase = (size_t)nc * HW4 + (size_t)h0 * W4 + w4;
    out4[obase]      = ob;
    out4[obase + W4] = oc;
}

extern "C" void kernel_launch(void* const* d_in, const int* in_sizes, int n_in,
                              void* d_out, int out_size)
{
    const float* x   = (const float*)d_in[0];
    const float* ker = (const float*)d_in[1];
    float* out = (float*)d_out;

    dynconv_kernel<<<TOTAL_THREADS / BLOCK, BLOCK>>>(x, ker, out);
}

// round 9
// speedup vs baseline: 1.2203x; 1.1224x over previous
#include <cuda_runtime.h>

// Dynamic per-pixel 5x5 conv (KPN) + leaky_relu(0.2), replicate padding.
// x:      (N=4, C=8, H=256, W=256) f32   -> d_in[0]
// kernel: (N=4, C*25=200, H=256, W=256)  -> d_in[1]
// out:    (N=4, C=8, H=256, W=256) f32
//
// R9: identical 2-row structure to R7, but launch_bounds (128,8): 64-reg
// budget at the SAME measured residency (~31-32 warps/SM), letting ptxas
// software-pipeline ~2x more LDG.128 kernel loads in flight. Tap streams for
// both output rows interleaved in one loop so the 10 independent plane loads
// per x-row are adjacent for hoisting.

#define NN   4
#define CC   8
#define HH   256
#define WW   256
#define KK   5
#define PAD  2
#define NEG_SLOPE 0.2f

#define W4   (WW / 4)           // 64
#define HW4  (HH * W4)          // 16384 float4 per plane
#define H2   (HH / 2)           // 128 row-pairs
#define TOTAL_THREADS (NN * CC * H2 * W4)   // 262144
#define BLOCK 128

__device__ __forceinline__ float lrelu(float v) {
    return v >= 0.f ? v : NEG_SLOPE * v;
}

__global__ __launch_bounds__(BLOCK, 8) void dynconv_kernel(
    const float* __restrict__ x,
    const float* __restrict__ ker,
    float* __restrict__ out)
{
    int tid = blockIdx.x * BLOCK + threadIdx.x;

    int w4   = tid & (W4 - 1);
    int hblk = (tid >> 6) & (H2 - 1);
    int nc   = tid >> 13;               // 0 .. N*C-1 (32)
    int h0   = hblk << 1;               // even row
    int w0   = w4 << 2;

    const float* xbase = x + (size_t)nc * (HH * WW);
    const float4* kbase0 = reinterpret_cast<const float4*>(ker)
                         + (size_t)nc * 25 * HW4
                         + (size_t)h0 * W4 + w4;
    const float4* kbase1 = kbase0 + W4;   // row h0+1

    // Accumulators: b -> row h0, c -> row h0+1
    float b0 = 0.f, b1 = 0.f, b2 = 0.f, b3 = 0.f;
    float c0 = 0.f, c1 = 0.f, c2 = 0.f, c3 = 0.f;

    // x rows h0-2 .. h0+3 serve taps of both output rows.
    #pragma unroll
    for (int rr = 0; rr < KK + 1; rr++) {
        int r = h0 + rr - PAD;
        r = max(0, min(HH - 1, r));
        const float* row = xbase + r * WW;

        float xv[8];
        #pragma unroll
        for (int i = 0; i < 8; i++) {
            int cidx = w0 + i - PAD;
            cidx = max(0, min(WW - 1, cidx));
            xv[i] = __ldg(row + cidx);
        }

        // Interleaved tap streams: k1 = rr for row h0 (rr 0..4),
        // k1 = rr-1 for row h0+1 (rr 1..5). Loads adjacent for hoisting.
        #pragma unroll
        for (int k2 = 0; k2 < KK; k2++) {
            if (rr < KK) {
                float4 kv = __ldcs(kbase0 + (size_t)(rr * KK + k2) * HW4);
                b0 = fmaf(xv[k2 + 0], kv.x, b0);
                b1 = fmaf(xv[k2 + 1], kv.y, b1);
                b2 = fmaf(xv[k2 + 2], kv.z, b2);
                b3 = fmaf(xv[k2 + 3], kv.w, b3);
            }
            if (rr >= 1) {
                float4 kv = __ldcs(kbase1 + (size_t)((rr - 1) * KK + k2) * HW4);
                c0 = fmaf(xv[k2 + 0], kv.x, c0);
                c1 = fmaf(xv[k2 + 1], kv.y, c1);
                c2 = fmaf(xv[k2 + 2], kv.z, c2);
                c3 = fmaf(xv[k2 + 3], kv.w, c3);
            }
        }
    }

    float4 ob, oc;
    ob.x = lrelu(b0); ob.y = lrelu(b1); ob.z = lrelu(b2); ob.w = lrelu(b3);
    oc.x = lrelu(c0); oc.y = lrelu(c1); oc.z = lrelu(c2); oc.w = lrelu(c3);

    float4* out4 = reinterpret_cast<float4*>(out);
    size_t obase = (size_t)nc * HW4 + (size_t)h0 * W4 + w4;
    out4[obase]      = ob;
    out4[obase + W4] = oc;
}

extern "C" void kernel_launch(void* const* d_in, const int* in_sizes, int n_in,
                              void* d_out, int out_size)
{
    const float* x   = (const float*)d_in[0];
    const float* ker = (const float*)d_in[1];
    float* out = (float*)d_out;

    dynconv_kernel<<<TOTAL_THREADS / BLOCK, BLOCK>>>(x, ker, out);
}